// round 2
// baseline (speedup 1.0000x reference)
#include <cuda_runtime.h>
#include <math.h>

#define NN   256
#define HWN  196
#define CC   512
#define KT   128
#define MT   64
#define KC   32
#define EPS_POS_F 0.65f
#define EPS_NEG_F 0.40f
#define INV_TAU   (1.0f/0.03f)
#define TEMP_F    0.07f

// Scratch (device globals: no allocation allowed in kernel_launch)
__device__ float g_aT[CC * NN];          // normalized audio, transposed [c][k]
__device__ float g_rnorm[NN * HWN];      // per frame-row rsqrt(sum sq)
__device__ float g_easy_num[NN * NN];    // sum_hw w*S   per (n,k)
__device__ float g_easy_den[NN * NN];    // sum_hw w     per (n,k)
__device__ float g_negnum[NN];
__device__ float g_negden[NN];
__device__ float g_Pid[NN];
__device__ float g_Nid[NN];

// ---------------------------------------------------------------------------
// Kernel A: normalize audio, store transposed for coalesced GEMM B loads
// ---------------------------------------------------------------------------
__global__ void k_audio(const float* __restrict__ audio) {
    int k = blockIdx.x;
    int tid = threadIdx.x;  // 128 threads
    float4 v = *(const float4*)(audio + (size_t)k * CC + tid * 4);
    float ss = v.x * v.x + v.y * v.y + v.z * v.z + v.w * v.w;
#pragma unroll
    for (int o = 16; o; o >>= 1) ss += __shfl_xor_sync(0xffffffffu, ss, o);
    __shared__ float sred[4];
    if ((tid & 31) == 0) sred[tid >> 5] = ss;
    __syncthreads();
    float rn = rsqrtf(sred[0] + sred[1] + sred[2] + sred[3]);
    int c = tid * 4;
    g_aT[(c + 0) * NN + k] = v.x * rn;
    g_aT[(c + 1) * NN + k] = v.y * rn;
    g_aT[(c + 2) * NN + k] = v.z * rn;
    g_aT[(c + 3) * NN + k] = v.w * rn;
}

// ---------------------------------------------------------------------------
// Kernel B: per frame-row inverse norm. One warp per row (512 floats).
// ---------------------------------------------------------------------------
__global__ void k_rnorm(const float* __restrict__ frame) {
    int warp = (blockIdx.x * blockDim.x + threadIdx.x) >> 5;
    int lane = threadIdx.x & 31;
    const float* row = frame + (size_t)warp * CC;
    float ss = 0.f;
#pragma unroll
    for (int p = 0; p < 4; p++) {
        float4 v = *(const float4*)(row + p * 128 + lane * 4);
        ss += v.x * v.x + v.y * v.y + v.z * v.z + v.w * v.w;
    }
#pragma unroll
    for (int o = 16; o; o >>= 1) ss += __shfl_xor_sync(0xffffffffu, ss, o);
    if (lane == 0) g_rnorm[warp] = rsqrtf(ss);
}

// ---------------------------------------------------------------------------
// Kernel C: fused GEMM + sigmoid-weighted reductions.
// Block = (kt, n). Computes S[n, hw, k0..k0+127] in register tiles and
// reduces over hw on the fly. Never materializes S.
// ---------------------------------------------------------------------------
__global__ void __launch_bounds__(256) k_main(const float* __restrict__ frame) {
    int kt = blockIdx.x;          // 0..1
    int n  = blockIdx.y;          // 0..255
    int k0 = kt * KT;
    int tid  = threadIdx.x;
    int kthr = tid >> 4;          // 0..15 -> 8 k each
    int mthr = tid & 15;          // 0..15 -> 4 m each

    __shared__ float sA[KC * 68];    // [c][m], padded row stride 68
    __shared__ float sB[KC * 128];   // [c][k]

    float wnum[8], wden[8];
#pragma unroll
    for (int j = 0; j < 8; j++) { wnum[j] = 0.f; wden[j] = 0.f; }
    float negnum = 0.f, negden = 0.f;
    int diag = n - k0;             // local diag column if 0..127
    int dj = diag - kthr * 8;      // this thread owns diag if 0..7

    const float* fbase = frame + (size_t)n * HWN * CC;
    int lm = tid >> 2;             // 0..63 : A loader row
    int lc = (tid & 3) * 8;        // 0,8,16,24 : A loader col offset

    for (int m0 = 0; m0 < HWN; m0 += MT) {
        float acc[4][8];
#pragma unroll
        for (int i = 0; i < 4; i++)
#pragma unroll
            for (int j = 0; j < 8; j++) acc[i][j] = 0.f;

        int mrow = m0 + lm;
        float rn = (mrow < HWN) ? g_rnorm[n * HWN + mrow] : 0.f;
        const float* rowp = fbase + (size_t)mrow * CC;

        for (int c0 = 0; c0 < CC; c0 += KC) {
            __syncthreads();
            // --- A tile: 64 rows x 32 c, normalized, stored transposed [c][m]
            float4 v0, v1;
            if (mrow < HWN) {
                v0 = *(const float4*)(rowp + c0 + lc);
                v1 = *(const float4*)(rowp + c0 + lc + 4);
            } else {
                v0 = make_float4(0.f, 0.f, 0.f, 0.f); v1 = v0;
            }
            sA[(lc + 0) * 68 + lm] = v0.x * rn;
            sA[(lc + 1) * 68 + lm] = v0.y * rn;
            sA[(lc + 2) * 68 + lm] = v0.z * rn;
            sA[(lc + 3) * 68 + lm] = v0.w * rn;
            sA[(lc + 4) * 68 + lm] = v1.x * rn;
            sA[(lc + 5) * 68 + lm] = v1.y * rn;
            sA[(lc + 6) * 68 + lm] = v1.z * rn;
            sA[(lc + 7) * 68 + lm] = v1.w * rn;
            // --- B tile: 32 c x 128 k straight copy from g_aT (coalesced)
#pragma unroll
            for (int r = 0; r < 4; r++) {
                int i = r * 1024 + tid * 4;
                int c = i >> 7;
                int kk = i & 127;
                float4 b = *(const float4*)(g_aT + (size_t)(c0 + c) * NN + k0 + kk);
                *(float4*)(sB + c * 128 + kk) = b;
            }
            __syncthreads();
            // --- 64x128 register-tiled FMA over this K chunk
#pragma unroll
            for (int c = 0; c < KC; c++) {
                float4 a  = *(const float4*)(sA + c * 68 + mthr * 4);
                float4 b0 = *(const float4*)(sB + c * 128 + kthr * 8);
                float4 b1 = *(const float4*)(sB + c * 128 + kthr * 8 + 4);
                float av[4] = {a.x, a.y, a.z, a.w};
                float bv[8] = {b0.x, b0.y, b0.z, b0.w, b1.x, b1.y, b1.z, b1.w};
#pragma unroll
                for (int im = 0; im < 4; im++)
#pragma unroll
                    for (int jk = 0; jk < 8; jk++)
                        acc[im][jk] = fmaf(av[im], bv[jk], acc[im][jk]);
            }
        }
        // --- fused epilogue: sigmoid weights + running reductions
#pragma unroll
        for (int im = 0; im < 4; im++) {
            int m = m0 + mthr * 4 + im;
            if (m < HWN) {
#pragma unroll
                for (int jk = 0; jk < 8; jk++) {
                    float S = acc[im][jk];
                    float w = __fdividef(1.f, 1.f + __expf((EPS_POS_F - S) * INV_TAU));
                    wnum[jk] += w * S;
                    wden[jk] += w;
                }
                if ((unsigned)dj < 8u) {
#pragma unroll
                    for (int jk = 0; jk < 8; jk++) {
                        if (jk == dj) {
                            float S = acc[im][jk];
                            float sp = __fdividef(1.f, 1.f + __expf((EPS_NEG_F - S) * INV_TAU));
                            float ng = 1.f - sp;
                            negnum += ng * S;
                            negden += ng;
                        }
                    }
                }
            }
        }
    }

    // --- block reduction over the 16 m-thread groups (reuse sB) ---
    __syncthreads();
#pragma unroll
    for (int j = 0; j < 8; j++) sB[mthr * 128 + kthr * 8 + j] = wnum[j];
    __syncthreads();
    if (tid < 128) {
        float s = 0.f;
#pragma unroll
        for (int r = 0; r < 16; r++) s += sB[r * 128 + tid];
        g_easy_num[(size_t)n * NN + k0 + tid] = s;
    }
    __syncthreads();
#pragma unroll
    for (int j = 0; j < 8; j++) sB[mthr * 128 + kthr * 8 + j] = wden[j];
    __syncthreads();
    if (tid < 128) {
        float s = 0.f;
#pragma unroll
        for (int r = 0; r < 16; r++) s += sB[r * 128 + tid];
        g_easy_den[(size_t)n * NN + k0 + tid] = s;
    }

    if ((unsigned)diag < 128u) {   // uniform per block
        __syncthreads();
        sA[tid] = negnum;
        sA[256 + tid] = negden;
        __syncthreads();
        for (int s = 128; s > 0; s >>= 1) {
            if (tid < s) {
                sA[tid] += sA[tid + s];
                sA[256 + tid] += sA[256 + tid + s];
            }
            __syncthreads();
        }
        if (tid == 0) { g_negnum[n] = sA[0]; g_negden[n] = sA[256]; }
    }
}

// ---------------------------------------------------------------------------
// Kernel D: per-n logits Pi_d[n], Ni_d[n].
// ---------------------------------------------------------------------------
__global__ void k_rowreduce() {
    int n = blockIdx.x;
    int tid = threadIdx.x;   // 256
    float num = g_easy_num[(size_t)n * NN + tid];
    float den = g_easy_den[(size_t)n * NN + tid];
    float ratio = num / den;
    float contrib = (tid == n) ? ratio * (-99.f) : ratio;
    __shared__ float sred[256];
    sred[tid] = contrib;
    __syncthreads();
    for (int s = 128; s > 0; s >>= 1) {
        if (tid < s) sred[tid] += sred[tid + s];
        __syncthreads();
    }
    if (tid == 0) {
        float r = sred[0];
        float Pi   = g_easy_num[(size_t)n * NN + n] / g_easy_den[(size_t)n * NN + n];
        float Nh   = g_negnum[n] / g_negden[n];
        g_Pid[n] = TEMP_F * Pi;
        g_Nid[n] = TEMP_F * (Nh + r);
    }
}

// ---------------------------------------------------------------------------
// Kernel E: final scalar. NOTE reference broadcasting: Pi_e is (N,1),
// Ni_e is (N,) -> Pi_e/(Pi_e+Ni_e) is (N,N). Sum over all pairs.
// loss = (1/N) * sum_{n,k} log1p(exp(Ni_d[k] - Pi_d[n]))
// ---------------------------------------------------------------------------
__global__ void k_loss(float* __restrict__ out) {
    int tid = threadIdx.x;   // 256: thread handles row n = tid
    __shared__ float sNid[256];
    sNid[tid] = g_Nid[tid];
    __syncthreads();
    float pid = g_Pid[tid];
    float acc = 0.f;
#pragma unroll 8
    for (int k = 0; k < NN; k++) {
        acc += log1pf(__expf(sNid[k] - pid));
    }
    __shared__ float sred[256];
    sred[tid] = acc;
    __syncthreads();
    for (int s = 128; s > 0; s >>= 1) {
        if (tid < s) sred[tid] += sred[tid + s];
        __syncthreads();
    }
    if (tid == 0) out[0] = sred[0] * (1.0f / NN);
}

extern "C" void kernel_launch(void* const* d_in, const int* in_sizes, int n_in,
                              void* d_out, int out_size) {
    const float* frame = (const float*)d_in[0];
    const float* audio = (const float*)d_in[1];
    if (n_in >= 2 && in_sizes[0] < in_sizes[1]) {  // defensive: frame is the big one
        frame = (const float*)d_in[1];
        audio = (const float*)d_in[0];
    }
    float* out = (float*)d_out;

    k_audio<<<NN, 128>>>(audio);
    k_rnorm<<<(NN * HWN) / 8, 256>>>(frame);
    dim3 g(2, NN);
    k_main<<<g, 256>>>(frame);
    k_rowreduce<<<NN, 256>>>();
    k_loss<<<1, 256>>>(out);
}

// round 4
// speedup vs baseline: 3.0098x; 3.0098x over previous
#include <cuda_runtime.h>
#include <cstdint>
#include <math.h>

#define NN   256
#define HWN  196
#define CC   512
#define EPS_POS_F 0.65f
#define EPS_NEG_F 0.40f
#define INV_TAU   (1.0f/0.03f)
#define TEMP_F    0.07f

#define LDA 36            // smem row stride in floats (conflict-free, 16B-aligned)
#define STAGE_F 12672     // floats per stage: (128 + 224) * 36 = 12672
#define SA_F 0            // A tile offset within stage (128 rows)
#define SB_F (128*LDA)    // B tile offset within stage (224 rows)
#define NRM_F  (3*STAGE_F)            // float[224]
#define RNS_F  (NRM_F + 224)          // float[224]
#define SNUM_F (RNS_F + 224)          // float[128]
#define SDEN_F (SNUM_F + 128)         // float[128]
#define SNEG_F (SDEN_F + 128)         // float[2]
#define SMEM_TOTAL ((SNEG_F + 8) * 4)

// ---- scratch globals ----
__device__ float g_aN[NN * CC];       // normalized audio (tf32-rounded), row-major
__device__ float g_easy_num[NN * NN];
__device__ float g_easy_den[NN * NN];
__device__ float g_negnum[NN];
__device__ float g_negden[NN];
__device__ float g_Pid[NN];
__device__ float g_Nid[NN];

__device__ __forceinline__ uint32_t smem_u32(const void* p) {
    uint32_t a;
    asm("{ .reg .u64 t; cvta.to.shared.u64 t, %1; cvt.u32.u64 %0, t; }" : "=r"(a) : "l"(p));
    return a;
}

#define CP_ASYNC16(dst, src) \
    asm volatile("cp.async.cg.shared.global [%0], [%1], 16;" :: "r"(dst), "l"(src) : "memory")
#define CP_ASYNC16Z(dst, src, sz) \
    asm volatile("cp.async.cg.shared.global [%0], [%1], 16, %2;" :: "r"(dst), "l"(src), "r"(sz) : "memory")
#define CP_COMMIT() asm volatile("cp.async.commit_group;" ::: "memory")
#define CP_WAIT2()  asm volatile("cp.async.wait_group 2;" ::: "memory")

#define MMA_TF32(d, a, b0, b1)                                                  \
    asm volatile("mma.sync.aligned.m16n8k8.row.col.f32.tf32.tf32.f32 "          \
        "{%0,%1,%2,%3}, {%4,%5,%6,%7}, {%8,%9}, {%0,%1,%2,%3};"                 \
        : "+f"((d)[0]), "+f"((d)[1]), "+f"((d)[2]), "+f"((d)[3])                \
        : "r"((a)[0]), "r"((a)[1]), "r"((a)[2]), "r"((a)[3]), "r"(b0), "r"(b1))

// ---------------------------------------------------------------------------
// Kernel A: normalize audio, round to tf32, store fp32 row-major
// ---------------------------------------------------------------------------
__global__ void k_audio(const float* __restrict__ audio) {
    int k = blockIdx.x;
    int tid = threadIdx.x;  // 128
    float4 v = *(const float4*)(audio + (size_t)k * CC + tid * 4);
    float ss = v.x * v.x + v.y * v.y + v.z * v.z + v.w * v.w;
#pragma unroll
    for (int o = 16; o; o >>= 1) ss += __shfl_xor_sync(0xffffffffu, ss, o);
    __shared__ float sred[4];
    if ((tid & 31) == 0) sred[tid >> 5] = ss;
    __syncthreads();
    float rn = rsqrtf(sred[0] + sred[1] + sred[2] + sred[3]);
    float o0 = v.x * rn, o1 = v.y * rn, o2 = v.z * rn, o3 = v.w * rn;
    uint32_t t0, t1, t2, t3;
    asm("cvt.rna.tf32.f32 %0, %1;" : "=r"(t0) : "f"(o0));
    asm("cvt.rna.tf32.f32 %0, %1;" : "=r"(t1) : "f"(o1));
    asm("cvt.rna.tf32.f32 %0, %1;" : "=r"(t2) : "f"(o2));
    asm("cvt.rna.tf32.f32 %0, %1;" : "=r"(t3) : "f"(o3));
    float4 w = make_float4(__uint_as_float(t0), __uint_as_float(t1),
                           __uint_as_float(t2), __uint_as_float(t3));
    *(float4*)(g_aN + (size_t)k * CC + tid * 4) = w;
}

// ---------------------------------------------------------------------------
// Main kernel: CTA (kt, n) computes S[n, aud kt*128..+128, hw 0..196] via
// tf32 mma.sync, with frame norms accumulated from smem and the sigmoid
// reductions fused in the epilogue. Frame never materialized/normalized.
// ---------------------------------------------------------------------------
__global__ void __launch_bounds__(256) k_mainTC(const float* __restrict__ frame) {
    extern __shared__ char smem_raw[];
    float* sm = (float*)smem_raw;
    uint32_t sb = smem_u32(smem_raw);

    int tid = threadIdx.x;
    int lane = tid & 31;
    int w = tid >> 5;
    int kt = blockIdx.x;       // 0..1
    int n  = blockIdx.y;       // 0..255
    int aud0 = kt * 128;

    const float* fbase = frame + (size_t)n * HWN * CC;
    const float* abase = g_aN + (size_t)aud0 * CC;

    int aud_off = (w >> 2) * 64;   // warp aud offset (0 or 64)
    int hw_off  = (w & 3) * 56;    // warp hw offset (0,56,112,168)
    int gID = lane >> 2;
    int tig = lane & 3;

    // pre-compute this thread's loader indices
    // A: 4 float4/chunk, B: 7 float4/chunk
    int la_r[4], la_s[4], lb_r[7], lb_s[7];
#pragma unroll
    for (int j = 0; j < 4; j++) { int idx = tid + j * 256; la_r[j] = idx >> 3; la_s[j] = idx & 7; }
#pragma unroll
    for (int j = 0; j < 7; j++) { int idx = tid + j * 256; lb_r[j] = idx >> 3; lb_s[j] = idx & 7; }

#define ISSUE(CH) do {                                                              \
    int _ch = (CH);                                                                  \
    if (_ch < 16) {                                                                  \
        int _st = _ch % 3;                                                           \
        uint32_t _sa = sb + _st * (STAGE_F * 4);                                     \
        uint32_t _sbb = _sa + SB_F * 4;                                              \
        int _c0 = _ch * 32;                                                          \
        _Pragma("unroll")                                                            \
        for (int j = 0; j < 4; j++) {                                                \
            const float* src = abase + (size_t)la_r[j] * CC + _c0 + la_s[j] * 4;     \
            CP_ASYNC16(_sa + la_r[j] * (LDA*4) + la_s[j] * 16, src);                 \
        }                                                                            \
        _Pragma("unroll")                                                            \
        for (int j = 0; j < 7; j++) {                                                \
            int rv = lb_r[j] < HWN ? lb_r[j] : HWN - 1;                              \
            int sz = lb_r[j] < HWN ? 16 : 0;                                         \
            const float* src = fbase + (size_t)rv * CC + _c0 + lb_s[j] * 4;          \
            CP_ASYNC16Z(_sbb + lb_r[j] * (LDA*4) + lb_s[j] * 16, src, sz);           \
        }                                                                            \
    }                                                                                \
    CP_COMMIT();                                                                     \
} while (0)

    ISSUE(0); ISSUE(1); ISSUE(2);

    float acc[4][7][4];
#pragma unroll
    for (int mt = 0; mt < 4; mt++)
#pragma unroll
        for (int nt = 0; nt < 7; nt++)
#pragma unroll
            for (int e = 0; e < 4; e++) acc[mt][nt][e] = 0.f;
    float nrm[7];
#pragma unroll
    for (int j = 0; j < 7; j++) nrm[j] = 0.f;

    for (int ch = 0; ch < 16; ch++) {
        int st = ch % 3;
        float* A = sm + st * STAGE_F;
        float* B = A + SB_F;
        CP_WAIT2();
        __syncthreads();

        // frame row-norm partials from smem (raw fp32; pad rows are zero)
#pragma unroll
        for (int j = 0; j < 7; j++) {
            float4 v = *(const float4*)(B + lb_r[j] * LDA + lb_s[j] * 4);
            nrm[j] += v.x * v.x + v.y * v.y + v.z * v.z + v.w * v.w;
        }

        // 4 k-steps of m16n8k8 tf32
#pragma unroll
        for (int ks = 0; ks < 4; ks++) {
            int kc = ks * 8 + tig;
            uint32_t a[4][4];
#pragma unroll
            for (int mt = 0; mt < 4; mt++) {
                int r = aud_off + mt * 16 + gID;
                a[mt][0] = __float_as_uint(A[r * LDA + kc]);
                a[mt][1] = __float_as_uint(A[(r + 8) * LDA + kc]);
                a[mt][2] = __float_as_uint(A[r * LDA + kc + 4]);
                a[mt][3] = __float_as_uint(A[(r + 8) * LDA + kc + 4]);
            }
#pragma unroll
            for (int nt = 0; nt < 7; nt++) {
                int hr = hw_off + nt * 8 + gID;
                uint32_t b0 = __float_as_uint(B[hr * LDA + kc]);
                uint32_t b1 = __float_as_uint(B[hr * LDA + kc + 4]);
#pragma unroll
                for (int mt = 0; mt < 4; mt++) MMA_TF32(acc[mt][nt], a[mt], b0, b1);
            }
        }
        __syncthreads();
        ISSUE(ch + 3);
    }

    // ---- finalize frame norms ----
#pragma unroll
    for (int j = 0; j < 7; j++) {
        float v = nrm[j];
        v += __shfl_xor_sync(0xffffffffu, v, 1, 8);
        v += __shfl_xor_sync(0xffffffffu, v, 2, 8);
        v += __shfl_xor_sync(0xffffffffu, v, 4, 8);
        if ((tid & 7) == 0) sm[NRM_F + (tid >> 3) + j * 32] = v;
    }
    __syncthreads();
    if (tid < 224) {
        float s = sm[NRM_F + tid];
        sm[RNS_F + tid] = (tid < HWN) ? rsqrtf(s) : 0.f;
    }
    if (tid < 128) { sm[SNUM_F + tid] = 0.f; sm[SDEN_F + tid] = 0.f; }
    if (tid == 0) { sm[SNEG_F] = 0.f; sm[SNEG_F + 1] = 0.f; }
    __syncthreads();

    // ---- fused sigmoid epilogue ----
    int diagL = n - aud0;    // valid if 0..127
#pragma unroll
    for (int mt = 0; mt < 4; mt++) {
        int r0 = aud_off + mt * 16 + gID;
#pragma unroll
        for (int half = 0; half < 2; half++) {
            int r = r0 + half * 8;
            bool isd = (r == diagL);
            float pn = 0.f, pd = 0.f, qn = 0.f, qd = 0.f;
#pragma unroll
            for (int nt = 0; nt < 7; nt++) {
#pragma unroll
                for (int e = 0; e < 2; e++) {
                    int c = hw_off + nt * 8 + tig * 2 + e;
                    if (c < HWN) {
                        float S = acc[mt][nt][half * 2 + e] * sm[RNS_F + c];
                        float wg = __fdividef(1.f, 1.f + __expf((EPS_POS_F - S) * INV_TAU));
                        pn += wg * S;
                        pd += wg;
                        if (isd) {
                            float sp = __fdividef(1.f, 1.f + __expf((EPS_NEG_F - S) * INV_TAU));
                            float ng = 1.f - sp;
                            qn += ng * S;
                            qd += ng;
                        }
                    }
                }
            }
#pragma unroll
            for (int o = 1; o < 4; o <<= 1) {
                pn += __shfl_xor_sync(0xffffffffu, pn, o, 4);
                pd += __shfl_xor_sync(0xffffffffu, pd, o, 4);
                qn += __shfl_xor_sync(0xffffffffu, qn, o, 4);
                qd += __shfl_xor_sync(0xffffffffu, qd, o, 4);
            }
            if (tig == 0) {
                atomicAdd(&sm[SNUM_F + r], pn);
                atomicAdd(&sm[SDEN_F + r], pd);
                if (isd) { atomicAdd(&sm[SNEG_F], qn); atomicAdd(&sm[SNEG_F + 1], qd); }
            }
        }
    }
    __syncthreads();
    if (tid < 128) {
        g_easy_num[(size_t)n * NN + aud0 + tid] = sm[SNUM_F + tid];
        g_easy_den[(size_t)n * NN + aud0 + tid] = sm[SDEN_F + tid];
    }
    if (tid == 0 && (unsigned)diagL < 128u) {
        g_negnum[n] = sm[SNEG_F];
        g_negden[n] = sm[SNEG_F + 1];
    }
}

// ---------------------------------------------------------------------------
// Kernel D: per-n logits Pi_d, Ni_d
// ---------------------------------------------------------------------------
__global__ void k_rowreduce() {
    int n = blockIdx.x;
    int tid = threadIdx.x;   // 256
    float num = g_easy_num[(size_t)n * NN + tid];
    float den = g_easy_den[(size_t)n * NN + tid];
    float ratio = num / den;
    float contrib = (tid == n) ? ratio * (-99.f) : ratio;
    __shared__ float sred[256];
    sred[tid] = contrib;
    __syncthreads();
    for (int s = 128; s > 0; s >>= 1) {
        if (tid < s) sred[tid] += sred[tid + s];
        __syncthreads();
    }
    if (tid == 0) {
        float r = sred[0];
        float Pi = g_easy_num[(size_t)n * NN + n] / g_easy_den[(size_t)n * NN + n];
        float Nh = g_negnum[n] / g_negden[n];
        g_Pid[n] = TEMP_F * Pi;
        g_Nid[n] = TEMP_F * (Nh + r);
    }
}

// ---------------------------------------------------------------------------
// Kernel E: reference's (N,1)+(N,) broadcast -> sum over all (n,k) pairs.
// ---------------------------------------------------------------------------
__global__ void k_loss(float* __restrict__ out) {
    int tid = threadIdx.x;   // 256
    __shared__ float sNid[256];
    sNid[tid] = g_Nid[tid];
    __syncthreads();
    float pid = g_Pid[tid];
    float acc = 0.f;
#pragma unroll 8
    for (int k = 0; k < NN; k++) acc += log1pf(__expf(sNid[k] - pid));
    __shared__ float sred[256];
    sred[tid] = acc;
    __syncthreads();
    for (int s = 128; s > 0; s >>= 1) {
        if (tid < s) sred[tid] += sred[tid + s];
        __syncthreads();
    }
    if (tid == 0) out[0] = sred[0] * (1.0f / NN);
}

extern "C" void kernel_launch(void* const* d_in, const int* in_sizes, int n_in,
                              void* d_out, int out_size) {
    const float* frame = (const float*)d_in[0];
    const float* audio = (const float*)d_in[1];
    if (n_in >= 2 && in_sizes[0] < in_sizes[1]) {
        frame = (const float*)d_in[1];
        audio = (const float*)d_in[0];
    }
    float* out = (float*)d_out;

    cudaFuncSetAttribute(k_mainTC, cudaFuncAttributeMaxDynamicSharedMemorySize, SMEM_TOTAL);

    k_audio<<<NN, 128>>>(audio);
    dim3 g(2, NN);
    k_mainTC<<<g, 256, SMEM_TOTAL>>>(frame);
    k_rowreduce<<<NN, 256>>>();
    k_loss<<<1, 256>>>(out);
}

// round 5
// speedup vs baseline: 3.8612x; 1.2829x over previous
#include <cuda_runtime.h>
#include <cuda_fp16.h>
#include <cstdint>
#include <math.h>

#define NN   256
#define HWN  196
#define CC   512
#define HWH  98            // real hw rows per half
#define HWP  112           // padded hw rows per half (14 x n8)
#define EPS_POS_F 0.65f
#define EPS_NEG_F 0.40f
#define INV_TAU   (1.0f/0.03f)
#define TEMP_F    0.07f

// ---- smem layout (bytes) ----
#define A_STAGE   20480        // 256 rows x 80 B (40 fp16, stride-padded)
#define BST_STAGE 16128        // 112 rows x 144 B (36 fp32)
#define SM_A(st)   ((st)*A_STAGE)
#define SM_BST(st) (61440 + (st)*BST_STAGE)
#define SM_BF16    109824      // 112 rows x 80 B fp16
#define SM_SNORM   118784      // float[112]
#define SM_RNS     119232      // float[112]
#define SM_SNUM    119680      // float[256]
#define SM_SDEN    120704      // float[256]
#define SM_SNEG    121728      // float[2]
#define SMEM_TOTAL 121760

// ---- scratch globals ----
__device__ __half g_aH[NN * CC];          // normalized audio fp16
__device__ float g_pn[2 * NN * NN];       // per-half partial num
__device__ float g_pd[2 * NN * NN];       // per-half partial den
__device__ float g_qn[2 * NN];            // per-half partial negnum
__device__ float g_qd[2 * NN];
__device__ float g_Pid[NN];
__device__ float g_Nid[NN];

__device__ __forceinline__ uint32_t smem_u32(const void* p) {
    uint32_t a;
    asm("{ .reg .u64 t; cvta.to.shared.u64 t, %1; cvt.u32.u64 %0, t; }" : "=r"(a) : "l"(p));
    return a;
}

#define CP_ASYNC16(dst, src) \
    asm volatile("cp.async.cg.shared.global [%0], [%1], 16;" :: "r"(dst), "l"(src) : "memory")
#define CP_ASYNC16Z(dst, src, sz) \
    asm volatile("cp.async.cg.shared.global [%0], [%1], 16, %2;" :: "r"(dst), "l"(src), "r"(sz) : "memory")
#define CP_COMMIT() asm volatile("cp.async.commit_group;" ::: "memory")
#define CP_WAIT2()  asm volatile("cp.async.wait_group 2;" ::: "memory")

#define MMA_FP16(d, a, b0, b1)                                                  \
    asm volatile("mma.sync.aligned.m16n8k16.row.col.f32.f16.f16.f32 "           \
        "{%0,%1,%2,%3}, {%4,%5,%6,%7}, {%8,%9}, {%0,%1,%2,%3};"                 \
        : "+f"((d)[0]), "+f"((d)[1]), "+f"((d)[2]), "+f"((d)[3])                \
        : "r"((a)[0]), "r"((a)[1]), "r"((a)[2]), "r"((a)[3]), "r"(b0), "r"(b1))

// ---------------------------------------------------------------------------
// Kernel A: normalize audio -> fp16 row-major [k][c]
// ---------------------------------------------------------------------------
__global__ void k_audio(const float* __restrict__ audio) {
    int k = blockIdx.x;
    int tid = threadIdx.x;  // 128
    float4 v = *(const float4*)(audio + (size_t)k * CC + tid * 4);
    float ss = v.x * v.x + v.y * v.y + v.z * v.z + v.w * v.w;
#pragma unroll
    for (int o = 16; o; o >>= 1) ss += __shfl_xor_sync(0xffffffffu, ss, o);
    __shared__ float sred[4];
    if ((tid & 31) == 0) sred[tid >> 5] = ss;
    __syncthreads();
    float rn = rsqrtf(sred[0] + sred[1] + sred[2] + sred[3]);
    __half2 p0 = __float22half2_rn(make_float2(v.x * rn, v.y * rn));
    __half2 p1 = __float22half2_rn(make_float2(v.z * rn, v.w * rn));
    uint2 u;
    u.x = *reinterpret_cast<uint32_t*>(&p0);
    u.y = *reinterpret_cast<uint32_t*>(&p1);
    *(uint2*)(g_aH + (size_t)k * CC + tid * 4) = u;
}

// ---------------------------------------------------------------------------
// Main kernel: CTA (h, n) computes S[n, aud 0..255, hw half h] via fp16
// m16n8k16 mma.sync. Frame converted fp32->fp16 in-loop; row norms from
// raw fp32; sigmoid reductions fused. Frame read from DRAM exactly once.
// ---------------------------------------------------------------------------
__global__ void __launch_bounds__(256) k_mainTC(const float* __restrict__ frame) {
    extern __shared__ char sm[];
    uint32_t sb = smem_u32(sm);
    int tid = threadIdx.x;
    int lane = tid & 31;
    int w = tid >> 5;
    int gID = lane >> 2;
    int tig = lane & 3;
    int h = blockIdx.x;        // 0..1 hw half
    int n = blockIdx.y;        // 0..255

    const float* fbase = frame + ((size_t)n * HWN + h * HWH) * CC;
    int aud_off = (w >> 1) * 64;   // 4 aud groups of 64 rows
    int hw_off  = (w & 1) * 56;    // 2 hw groups of 56 cols

#define ISSUE(CH) do {                                                              \
    int _c = (CH);                                                                   \
    if (_c < 16) {                                                                   \
        int _st = _c % 3;                                                            \
        int _c0 = _c * 32;                                                           \
        uint32_t _a = sb + SM_A(_st);                                                \
        uint32_t _b = sb + SM_BST(_st);                                              \
        _Pragma("unroll")                                                            \
        for (int j = 0; j < 4; j++) {                                                \
            int i = tid + j * 256;                                                   \
            int r = i >> 2, s = i & 3;                                               \
            CP_ASYNC16(_a + r * 80 + s * 16, g_aH + (size_t)r * CC + _c0 + s * 8);   \
        }                                                                            \
        _Pragma("unroll")                                                            \
        for (int j = 0; j < 4; j++) {                                                \
            int i = tid + j * 256;                                                   \
            if (i < 896) {                                                           \
                int r = i >> 3, s = i & 7;                                           \
                int rv = r < HWH ? r : HWH - 1;                                      \
                int sz = r < HWH ? 16 : 0;                                           \
                CP_ASYNC16Z(_b + r * 144 + s * 16,                                   \
                            fbase + (size_t)rv * CC + _c0 + s * 4, sz);              \
            }                                                                        \
        }                                                                            \
    }                                                                                \
    CP_COMMIT();                                                                     \
} while (0)

    ISSUE(0); ISSUE(1); ISSUE(2);

    float acc[4][7][4];
#pragma unroll
    for (int mt = 0; mt < 4; mt++)
#pragma unroll
        for (int nt = 0; nt < 7; nt++)
#pragma unroll
            for (int e = 0; e < 4; e++) acc[mt][nt][e] = 0.f;
    float nrm[4];
#pragma unroll
    for (int j = 0; j < 4; j++) nrm[j] = 0.f;

    for (int ch = 0; ch < 16; ch++) {
        int st = ch % 3;
        CP_WAIT2();
        __syncthreads();

        // ---- convert fp32 staging -> fp16 B + norm accumulation ----
#pragma unroll
        for (int j = 0; j < 4; j++) {
            int i = tid + j * 256;
            if (i < 896) {
                int r = i >> 3, s = i & 7;
                float4 v = *(const float4*)(sm + SM_BST(st) + r * 144 + s * 16);
                __half2 h01 = __float22half2_rn(make_float2(v.x, v.y));
                __half2 h23 = __float22half2_rn(make_float2(v.z, v.w));
                uint2 u;
                u.x = *reinterpret_cast<uint32_t*>(&h01);
                u.y = *reinterpret_cast<uint32_t*>(&h23);
                *(uint2*)(sm + SM_BF16 + r * 80 + s * 8) = u;
                nrm[j] += v.x * v.x + v.y * v.y + v.z * v.z + v.w * v.w;
            }
        }
        __syncthreads();

        // ---- MMA phase: 2 k16-steps ----
        const char* Ab = sm + SM_A(st);
        const char* Bb = sm + SM_BF16;
#pragma unroll
        for (int ks = 0; ks < 2; ks++) {
            int kb = (ks * 16 + 2 * tig) * 2;    // byte offset of k pair
            uint32_t a[4][4];
#pragma unroll
            for (int mt = 0; mt < 4; mt++) {
                int r = aud_off + mt * 16 + gID;
                a[mt][0] = *(const uint32_t*)(Ab + r * 80 + kb);
                a[mt][1] = *(const uint32_t*)(Ab + (r + 8) * 80 + kb);
                a[mt][2] = *(const uint32_t*)(Ab + r * 80 + kb + 16);
                a[mt][3] = *(const uint32_t*)(Ab + (r + 8) * 80 + kb + 16);
            }
#pragma unroll
            for (int nt = 0; nt < 7; nt++) {
                int nr = hw_off + nt * 8 + gID;
                uint32_t b0 = *(const uint32_t*)(Bb + nr * 80 + kb);
                uint32_t b1 = *(const uint32_t*)(Bb + nr * 80 + kb + 16);
#pragma unroll
                for (int mt = 0; mt < 4; mt++) MMA_FP16(acc[mt][nt], a[mt], b0, b1);
            }
        }
        __syncthreads();
        ISSUE(ch + 3);
    }

    // ---- finalize frame norms ----
    float* snorm = (float*)(sm + SM_SNORM);
    float* rns   = (float*)(sm + SM_RNS);
    float* snum  = (float*)(sm + SM_SNUM);
    float* sden  = (float*)(sm + SM_SDEN);
    float* sneg  = (float*)(sm + SM_SNEG);
#pragma unroll
    for (int j = 0; j < 4; j++) {
        int i = tid + j * 256;
        if (i < 896) {
            float v = nrm[j];
            v += __shfl_xor_sync(0xffffffffu, v, 1, 8);
            v += __shfl_xor_sync(0xffffffffu, v, 2, 8);
            v += __shfl_xor_sync(0xffffffffu, v, 4, 8);
            if ((tid & 7) == 0) snorm[i >> 3] = v;
        }
    }
    __syncthreads();
    if (tid < HWP) rns[tid] = (tid < HWH) ? rsqrtf(snorm[tid]) : 0.f;
    snum[tid] = 0.f;
    sden[tid] = 0.f;
    if (tid == 0) { sneg[0] = 0.f; sneg[1] = 0.f; }
    __syncthreads();

    // ---- fused sigmoid epilogue ----
#pragma unroll
    for (int mt = 0; mt < 4; mt++) {
        int r0 = aud_off + mt * 16 + gID;
#pragma unroll
        for (int half = 0; half < 2; half++) {
            int r = r0 + half * 8;           // audio index k
            bool isd = (r == n);
            float pn = 0.f, pd = 0.f, qn = 0.f, qd = 0.f;
#pragma unroll
            for (int nt = 0; nt < 7; nt++) {
#pragma unroll
                for (int e = 0; e < 2; e++) {
                    int c = hw_off + nt * 8 + tig * 2 + e;
                    if (c < HWH) {
                        float S = acc[mt][nt][half * 2 + e] * rns[c];
                        float wg = __fdividef(1.f, 1.f + __expf((EPS_POS_F - S) * INV_TAU));
                        pn += wg * S;
                        pd += wg;
                        if (isd) {
                            float sp = __fdividef(1.f, 1.f + __expf((EPS_NEG_F - S) * INV_TAU));
                            float ng = 1.f - sp;
                            qn += ng * S;
                            qd += ng;
                        }
                    }
                }
            }
#pragma unroll
            for (int o = 1; o < 4; o <<= 1) {
                pn += __shfl_xor_sync(0xffffffffu, pn, o, 4);
                pd += __shfl_xor_sync(0xffffffffu, pd, o, 4);
                qn += __shfl_xor_sync(0xffffffffu, qn, o, 4);
                qd += __shfl_xor_sync(0xffffffffu, qd, o, 4);
            }
            if (tig == 0) {
                atomicAdd(&snum[r], pn);
                atomicAdd(&sden[r], pd);
                if (isd) { atomicAdd(&sneg[0], qn); atomicAdd(&sneg[1], qd); }
            }
        }
    }
    __syncthreads();
    g_pn[(size_t)h * NN * NN + (size_t)n * NN + tid] = snum[tid];
    g_pd[(size_t)h * NN * NN + (size_t)n * NN + tid] = sden[tid];
    if (tid == 0) {
        g_qn[h * NN + n] = sneg[0];
        g_qd[h * NN + n] = sneg[1];
    }
}

// ---------------------------------------------------------------------------
// Kernel D: per-n logits Pi_d, Ni_d (sum the two hw-half partials)
// ---------------------------------------------------------------------------
__global__ void k_rowreduce() {
    int n = blockIdx.x;
    int tid = threadIdx.x;   // 256
    float num = g_pn[(size_t)n * NN + tid] + g_pn[NN * NN + (size_t)n * NN + tid];
    float den = g_pd[(size_t)n * NN + tid] + g_pd[NN * NN + (size_t)n * NN + tid];
    float ratio = num / den;
    __shared__ float sPi[2];
    if (tid == n) { sPi[0] = num; sPi[1] = den; }
    float contrib = (tid == n) ? ratio * (-99.f) : ratio;
#pragma unroll
    for (int o = 16; o; o >>= 1) contrib += __shfl_xor_sync(0xffffffffu, contrib, o);
    __shared__ float sred[8];
    if ((tid & 31) == 0) sred[tid >> 5] = contrib;
    __syncthreads();
    if (tid == 0) {
        float r = 0.f;
#pragma unroll
        for (int i = 0; i < 8; i++) r += sred[i];
        float Pi = sPi[0] / sPi[1];
        float Nh = (g_qn[n] + g_qn[NN + n]) / (g_qd[n] + g_qd[NN + n]);
        g_Pid[n] = TEMP_F * Pi;
        g_Nid[n] = TEMP_F * (Nh + r);
    }
}

// ---------------------------------------------------------------------------
// Kernel E: reference's (N,1)+(N,) broadcast -> sum over all (n,k) pairs.
// loss = (1/N) * sum_{n,k} softplus(Ni_d[k] - Pi_d[n])
// ---------------------------------------------------------------------------
__global__ void k_loss(float* __restrict__ out) {
    int tid = threadIdx.x;   // 256
    __shared__ float sNid[256];
    sNid[tid] = g_Nid[tid];
    __syncthreads();
    float pid = g_Pid[tid];
    float acc = 0.f;
#pragma unroll 8
    for (int k = 0; k < NN; k++) {
        float x = sNid[k] - pid;
        float m = fmaxf(x, 0.f);
        acc += m + __logf(__expf(x - m) + __expf(-m));
    }
#pragma unroll
    for (int o = 16; o; o >>= 1) acc += __shfl_xor_sync(0xffffffffu, acc, o);
    __shared__ float sred[8];
    if ((tid & 31) == 0) sred[tid >> 5] = acc;
    __syncthreads();
    if (tid == 0) {
        float s = 0.f;
#pragma unroll
        for (int i = 0; i < 8; i++) s += sred[i];
        out[0] = s * (1.0f / NN);
    }
}

extern "C" void kernel_launch(void* const* d_in, const int* in_sizes, int n_in,
                              void* d_out, int out_size) {
    const float* frame = (const float*)d_in[0];
    const float* audio = (const float*)d_in[1];
    if (n_in >= 2 && in_sizes[0] < in_sizes[1]) {
        frame = (const float*)d_in[1];
        audio = (const float*)d_in[0];
    }
    float* out = (float*)d_out;

    cudaFuncSetAttribute(k_mainTC, cudaFuncAttributeMaxDynamicSharedMemorySize, SMEM_TOTAL);

    k_audio<<<NN, 128>>>(audio);
    dim3 g(2, NN);
    k_mainTC<<<g, 256, SMEM_TOTAL>>>(frame);
    k_rowreduce<<<NN, 256>>>();
    k_loss<<<1, 256>>>(out);
}